// round 2
// baseline (speedup 1.0000x reference)
#include <cuda_runtime.h>

#define NTHREADS 256

// Problem constants
constexpr int Bc = 512;
constexpr int Lc = 200;
constexpr int Ec = 64;
constexpr int Hc = 4;

// Shared memory layout (floats)
constexpr int KTS    = 225;                    // padded k-transposed stride (conflict-free)
constexpr int OFF_KT = 0;                      // Kt[64][225]  (Kt[e][t])
constexpr int OFF_QS = OFF_KT + Ec * KTS;      // Qs[200][64]
constexpr int OFF_VS = OFF_QS + Lc * Ec;       // Vs[200][64]
constexpr int OFF_WT = OFF_VS + Lc * Ec;       // Wt[3][64][64] transposed weights (k,v,q); reused for Wf later
constexpr int OFF_XS = OFF_WT + 3 * Ec * Ec;   // xs[32][64] tile staging
constexpr int OFF_W  = OFF_XS + 32 * Ec;       // wcol[4][200] attention column sums
constexpr int OFF_SP = OFF_W + Hc * Lc;        // Sp[4][64] partial sums
constexpr int OFF_SS = OFF_SP + 4 * Ec;        // Ss[64]
constexpr int SMEM_F = OFF_SS + Ec;            // total floats = 55456 -> 221824 bytes

static __device__ __forceinline__ float warp_max(float v) {
#pragma unroll
    for (int o = 16; o; o >>= 1) v = fmaxf(v, __shfl_xor_sync(0xffffffffu, v, o));
    return v;
}
static __device__ __forceinline__ float warp_sum(float v) {
#pragma unroll
    for (int o = 16; o; o >>= 1) v += __shfl_xor_sync(0xffffffffu, v, o);
    return v;
}

extern __shared__ float sw[];

__global__ void __launch_bounds__(NTHREADS, 1)
attn_pool_kernel(const float* __restrict__ input,
                 const int* __restrict__ mask,          // bool delivered as int32
                 const float* __restrict__ pos_enc,
                 const float* __restrict__ Wk, const float* __restrict__ bk,
                 const float* __restrict__ Wv, const float* __restrict__ bv,
                 const float* __restrict__ Wq, const float* __restrict__ bq,
                 const float* __restrict__ Wf, const float* __restrict__ bf,
                 float* __restrict__ out) {
    const int tid = threadIdx.x;
    const int b = blockIdx.x;
    const int lane = tid & 31;
    const int wid = tid >> 5;

    // ---- len = number of valid rows (prefix mask) ----
    int pred = (tid < Lc) && (mask[(size_t)b * Lc + tid] != 0);
    const int len = __syncthreads_count(pred);

    // ---- phase 0: transposed weights into smem + zero column-sum buffer ----
    for (int idx = tid; idx < Ec * Ec; idx += NTHREADS) {
        int e = idx >> 6, j = idx & 63;
        sw[OFF_WT + 0 * 4096 + j * 64 + e] = Wk[idx];
        sw[OFF_WT + 1 * 4096 + j * 64 + e] = Wv[idx];
        sw[OFF_WT + 2 * 4096 + j * 64 + e] = Wq[idx];
    }
    for (int idx = tid; idx < Hc * Lc; idx += NTHREADS) sw[OFF_W + idx] = 0.0f;
    __syncthreads();

    // ---- phase 1: x = input + pos_enc ; K,V,Q projections (only rows < len) ----
    const int e0 = (tid & 15) * 4;   // 4 output columns per thread
    const int r0 = (tid >> 4) * 2;   // 2 rows per thread within 32-row tile
    const float4 bk4 = *(const float4*)(bk + e0);
    const float4 bv4 = *(const float4*)(bv + e0);
    const float4 bq4 = *(const float4*)(bq + e0);

    const int ntiles = (len + 31) >> 5;
    for (int tile = 0; tile < ntiles; tile++) {
        const int tbase = tile * 32;
        // stage x tile (input + pos_enc), float4 coalesced
        {
            const float4* in4 = (const float4*)(input + ((size_t)b * Lc + tbase) * Ec);
            const float4* pe4 = (const float4*)(pos_enc + (size_t)tbase * Ec);
            float4* xs4 = (float4*)(sw + OFF_XS);
#pragma unroll
            for (int v = 0; v < 2; v++) {
                int fidx = tid + v * NTHREADS;       // 0..511
                int r = fidx >> 4;
                int t = tbase + r;
                float4 val = make_float4(0.f, 0.f, 0.f, 0.f);
                if (t < Lc) {
                    float4 a = in4[fidx];
                    float4 p = pe4[fidx];
                    val = make_float4(a.x + p.x, a.y + p.y, a.z + p.z, a.w + p.w);
                }
                xs4[fidx] = val;
            }
        }
        __syncthreads();

        float accK[2][4], accV[2][4], accQ[2][4];
#pragma unroll
        for (int rr = 0; rr < 2; rr++)
#pragma unroll
            for (int i = 0; i < 4; i++) { accK[rr][i] = 0.f; accV[rr][i] = 0.f; accQ[rr][i] = 0.f; }

#pragma unroll 8
        for (int j = 0; j < 64; j++) {
            float x0 = sw[OFF_XS + r0 * 64 + j];
            float x1 = sw[OFF_XS + (r0 + 1) * 64 + j];
            float4 wk4 = *(const float4*)(sw + OFF_WT + 0 * 4096 + j * 64 + e0);
            float4 wv4 = *(const float4*)(sw + OFF_WT + 1 * 4096 + j * 64 + e0);
            float4 wq4 = *(const float4*)(sw + OFF_WT + 2 * 4096 + j * 64 + e0);
            float wkv[4] = {wk4.x, wk4.y, wk4.z, wk4.w};
            float wvv[4] = {wv4.x, wv4.y, wv4.z, wv4.w};
            float wqv[4] = {wq4.x, wq4.y, wq4.z, wq4.w};
#pragma unroll
            for (int i = 0; i < 4; i++) {
                accK[0][i] = fmaf(x0, wkv[i], accK[0][i]);
                accK[1][i] = fmaf(x1, wkv[i], accK[1][i]);
                accV[0][i] = fmaf(x0, wvv[i], accV[0][i]);
                accV[1][i] = fmaf(x1, wvv[i], accV[1][i]);
                accQ[0][i] = fmaf(x0, wqv[i], accQ[0][i]);
                accQ[1][i] = fmaf(x1, wqv[i], accQ[1][i]);
            }
        }

        const float bkv[4] = {bk4.x, bk4.y, bk4.z, bk4.w};
        const float bvv[4] = {bv4.x, bv4.y, bv4.z, bv4.w};
        const float bqv[4] = {bq4.x, bq4.y, bq4.z, bq4.w};
#pragma unroll
        for (int rr = 0; rr < 2; rr++) {
            int t = tbase + r0 + rr;
            if (t < Lc) {
#pragma unroll
                for (int i = 0; i < 4; i++) {
                    int e = e0 + i;
                    sw[OFF_KT + e * KTS + t] = accK[rr][i] + bkv[i];
                    sw[OFF_VS + t * 64 + e]  = accV[rr][i] + bvv[i];
                    sw[OFF_QS + t * 64 + e]  = (accQ[rr][i] + bqv[i]) * 0.25f; // 1/sqrt(D)
                }
            }
        }
        __syncthreads();
    }

    // stage Wf (transposed) into the now-free Wt region for phase 4
    for (int idx = tid; idx < Ec * Ec; idx += NTHREADS) {
        int e = idx >> 6, c = idx & 63;
        sw[OFF_WT + c * 64 + e] = Wf[idx];
    }
    // (no sync needed yet; phase 2 doesn't touch OFF_WT; phase-3 sync covers it)

    // ---- phase 2: scores + exact softmax, accumulate attention column sums ----
    // warp handles 4 query rows per iteration; lanes span keys (k = lane + 32*m)
    for (int h = 0; h < Hc; h++) {
        float wacc[7];
#pragma unroll
        for (int m = 0; m < 7; m++) wacc[m] = 0.0f;

        for (int qb = wid * 4; qb < len; qb += 32) {
            // load 4 q rows (this head's 16 dims) into registers (broadcast LDS)
            float qv0[16], qv1[16], qv2[16], qv3[16];
            {
                int q0 = qb,     q1 = qb + 1, q2 = qb + 2, q3 = qb + 3;
                q0 = (q0 < len) ? q0 : 0; q1 = (q1 < len) ? q1 : 0;
                q2 = (q2 < len) ? q2 : 0; q3 = (q3 < len) ? q3 : 0;
                const float4* p0 = (const float4*)(sw + OFF_QS + q0 * 64 + h * 16);
                const float4* p1 = (const float4*)(sw + OFF_QS + q1 * 64 + h * 16);
                const float4* p2 = (const float4*)(sw + OFF_QS + q2 * 64 + h * 16);
                const float4* p3 = (const float4*)(sw + OFF_QS + q3 * 64 + h * 16);
#pragma unroll
                for (int jj = 0; jj < 4; jj++) {
                    float4 v0 = p0[jj]; qv0[4*jj]=v0.x; qv0[4*jj+1]=v0.y; qv0[4*jj+2]=v0.z; qv0[4*jj+3]=v0.w;
                    float4 v1 = p1[jj]; qv1[4*jj]=v1.x; qv1[4*jj+1]=v1.y; qv1[4*jj+2]=v1.z; qv1[4*jj+3]=v1.w;
                    float4 v2 = p2[jj]; qv2[4*jj]=v2.x; qv2[4*jj+1]=v2.y; qv2[4*jj+2]=v2.z; qv2[4*jj+3]=v2.w;
                    float4 v3 = p3[jj]; qv3[4*jj]=v3.x; qv3[4*jj+1]=v3.y; qv3[4*jj+2]=v3.z; qv3[4*jj+3]=v3.w;
                }
            }

            float s[7][4];
#pragma unroll
            for (int m = 0; m < 7; m++) {
                float s0 = -1e30f, s1 = -1e30f, s2 = -1e30f, s3 = -1e30f;
                int k = m * 32 + lane;
                if (k < len) {
                    const float* kp = sw + OFF_KT + (h * 16) * KTS + k;
                    float a0 = 0.f, a1 = 0.f, a2 = 0.f, a3 = 0.f;
#pragma unroll
                    for (int j = 0; j < 16; j++) {
                        float kw = kp[j * KTS];
                        a0 = fmaf(kw, qv0[j], a0);
                        a1 = fmaf(kw, qv1[j], a1);
                        a2 = fmaf(kw, qv2[j], a2);
                        a3 = fmaf(kw, qv3[j], a3);
                    }
                    s0 = a0; s1 = a1; s2 = a2; s3 = a3;
                }
                s[m][0] = s0; s[m][1] = s1; s[m][2] = s2; s[m][3] = s3;
            }

            // exact softmax per q; accumulate column sums into registers
#pragma unroll
            for (int qq = 0; qq < 4; qq++) {
                float mx = -1e30f;
#pragma unroll
                for (int m = 0; m < 7; m++) mx = fmaxf(mx, s[m][qq]);
                mx = warp_max(mx);
                float ee[7];
                float ssum = 0.f;
#pragma unroll
                for (int m = 0; m < 7; m++) { ee[m] = __expf(s[m][qq] - mx); ssum += ee[m]; }
                ssum = warp_sum(ssum);
                float sc = (qb + qq < len) ? __fdividef(1.0f, ssum) : 0.0f;
#pragma unroll
                for (int m = 0; m < 7; m++) wacc[m] = fmaf(ee[m], sc, wacc[m]);
            }
        }

        // fold this head's column sums into shared
#pragma unroll
        for (int m = 0; m < 7; m++) {
            int k = m * 32 + lane;
            if (k < Lc) atomicAdd(&sw[OFF_W + h * Lc + k], wacc[m]);
        }
    }
    __syncthreads();

    // ---- phase 3: S[c] = sum_k wcol[h(c)][k] * V[k][c] ----
    {
        const int c = tid & 63;
        const int part = tid >> 6;
        const int hh = c >> 4;
        float acc = 0.f;
        for (int k = part; k < len; k += 4)
            acc = fmaf(sw[OFF_W + hh * Lc + k], sw[OFF_VS + k * 64 + c], acc);
        sw[OFF_SP + part * 64 + c] = acc;
    }
    __syncthreads();
    if (tid < 64) {
        float s = sw[OFF_SP + tid] + sw[OFF_SP + 64 + tid] +
                  sw[OFF_SP + 128 + tid] + sw[OFF_SP + 192 + tid];
        sw[OFF_SS + tid] = s;
    }
    __syncthreads();

    // ---- phase 4: pooled[b][e] = (S . Wf[e,:]) / (len+1e-8) + bf[e]*len/(len+1e-8) ----
    if (tid < 64) {
        float acc = 0.f;
#pragma unroll 16
        for (int c = 0; c < 64; c++)
            acc = fmaf(sw[OFF_SS + c], sw[OFF_WT + c * 64 + tid], acc);
        float lenf = (float)len;
        float inv = 1.0f / (lenf + 1e-8f);
        out[b * 64 + tid] = acc * inv + bf[tid] * lenf * inv;
    }
}

extern "C" void kernel_launch(void* const* d_in, const int* in_sizes, int n_in,
                              void* d_out, int out_size) {
    const float* input   = (const float*)d_in[0];
    const int*   mask    = (const int*)d_in[1];
    const float* pos_enc = (const float*)d_in[2];
    const float* Wk      = (const float*)d_in[3];
    const float* bk      = (const float*)d_in[4];
    const float* Wv      = (const float*)d_in[5];
    const float* bv      = (const float*)d_in[6];
    const float* Wq      = (const float*)d_in[7];
    const float* bq      = (const float*)d_in[8];
    const float* Wf      = (const float*)d_in[9];
    const float* bf      = (const float*)d_in[10];
    float* out           = (float*)d_out;

    const size_t smem_bytes = (size_t)SMEM_F * sizeof(float);
    cudaFuncSetAttribute(attn_pool_kernel,
                         cudaFuncAttributeMaxDynamicSharedMemorySize,
                         (int)smem_bytes);
    attn_pool_kernel<<<Bc, NTHREADS, smem_bytes>>>(
        input, mask, pos_enc, Wk, bk, Wv, bv, Wq, bq, Wf, bf, out);
}

// round 3
// speedup vs baseline: 1.3306x; 1.3306x over previous
#include <cuda_runtime.h>

constexpr int Bc = 512;
constexpr int Lc = 200;
constexpr int Ec = 64;

// ---------------- kernel 1 smem layout (floats) ----------------
constexpr int WSS    = 20;                       // padded ws row stride
constexpr int WS_OFF = 0;                        // ws[3][64][20]: ws[m][j][i] = Wm[h*16+i][j]
constexpr int XSS    = 68;                       // padded x stride
constexpr int XS_OFF = WS_OFF + 3 * 64 * WSS;    // xs[64][68]
constexpr int KTS    = 208;                      // padded kt stride
constexpr int KT_OFF = XS_OFF + 64 * XSS;        // kt[16][208]
constexpr int QS_OFF = KT_OFF + 16 * KTS;        // q[200][16]
constexpr int VS_OFF = QS_OFF + Lc * 16;         // v[200][16]
constexpr int WC_OFF = VS_OFF + Lc * 16;         // col sums [200]
constexpr int SP_OFF = WC_OFF + Lc;              // partials [16][16]
constexpr int SM1_F  = SP_OFF + 256;             // ~18376 floats = 73.5 KB

__device__ float g_S[Bc * Ec];
__device__ int   g_len[Bc];

extern __shared__ float sw[];

__global__ void __launch_bounds__(256, 2)
attn_head_kernel(const float* __restrict__ input,
                 const int* __restrict__ mask,
                 const float* __restrict__ pos_enc,
                 const float* __restrict__ Wk, const float* __restrict__ bk,
                 const float* __restrict__ Wv, const float* __restrict__ bv,
                 const float* __restrict__ Wq, const float* __restrict__ bq) {
    const int tid  = threadIdx.x;
    const int lane = tid & 31;
    const int wid  = tid >> 5;
    const int b    = blockIdx.x >> 2;
    const int h    = blockIdx.x & 3;

    // ---- len (prefix mask; mask is int32) ----
    int pred = (tid < Lc) && (mask[(size_t)b * Lc + tid] != 0);
    const int len = __syncthreads_count(pred);

    // ---- phase 0: weight slices (transposed) for this head ----
    for (int idx = tid; idx < 64 * 16; idx += 256) {
        int j = idx & 63, i = idx >> 6;              // j consecutive -> coalesced LDG
        int g = (h * 16 + i) * 64 + j;
        sw[WS_OFF + 0 * 64 * WSS + j * WSS + i] = Wk[g];
        sw[WS_OFF + 1 * 64 * WSS + j * WSS + i] = Wv[g];
        sw[WS_OFF + 2 * 64 * WSS + j * WSS + i] = Wq[g];
    }
    if (tid < Lc) sw[WC_OFF + tid] = 0.0f;
    __syncthreads();

    // ---- phase 1: projection (tiles of 64 rows) ----
    const int r  = tid >> 2;          // row within tile
    const int c4 = (tid & 3) * 4;     // 4 output dims
    float4 bK = *(const float4*)(bk + h * 16 + c4);
    float4 bV = *(const float4*)(bv + h * 16 + c4);
    float4 bQ = *(const float4*)(bq + h * 16 + c4);

    const int ntiles = (len + 63) >> 6;
    for (int tile = 0; tile < ntiles; tile++) {
        const int tb = tile * 64;
        // stage x = input + pos_enc
        const float4* in4 = (const float4*)(input + ((size_t)b * Lc + tb) * Ec);
        const float4* pe4 = (const float4*)(pos_enc + (size_t)tb * Ec);
#pragma unroll
        for (int v = 0; v < 4; v++) {
            int f = tid + v * 256;                // 0..1023
            int rr = f >> 4, cc = (f & 15) * 4;
            float4 val = make_float4(0.f, 0.f, 0.f, 0.f);
            if (tb + rr < Lc) {
                float4 a = in4[f], p = pe4[f];
                val = make_float4(a.x + p.x, a.y + p.y, a.z + p.z, a.w + p.w);
            }
            *(float4*)(sw + XS_OFF + rr * XSS + cc) = val;
        }
        __syncthreads();

        float acc[3][4];
#pragma unroll
        for (int m = 0; m < 3; m++)
#pragma unroll
            for (int i = 0; i < 4; i++) acc[m][i] = 0.f;

#pragma unroll 8
        for (int j = 0; j < 64; j++) {
            float x = sw[XS_OFF + r * XSS + j];
#pragma unroll
            for (int m = 0; m < 3; m++) {
                float4 w = *(const float4*)(sw + WS_OFF + m * 64 * WSS + j * WSS + c4);
                acc[m][0] = fmaf(x, w.x, acc[m][0]);
                acc[m][1] = fmaf(x, w.y, acc[m][1]);
                acc[m][2] = fmaf(x, w.z, acc[m][2]);
                acc[m][3] = fmaf(x, w.w, acc[m][3]);
            }
        }

        const int t = tb + r;
        if (t < len) {
            sw[KT_OFF + (c4 + 0) * KTS + t] = acc[0][0] + bK.x;
            sw[KT_OFF + (c4 + 1) * KTS + t] = acc[0][1] + bK.y;
            sw[KT_OFF + (c4 + 2) * KTS + t] = acc[0][2] + bK.z;
            sw[KT_OFF + (c4 + 3) * KTS + t] = acc[0][3] + bK.w;
            *(float4*)(sw + VS_OFF + t * 16 + c4) =
                make_float4(acc[1][0] + bV.x, acc[1][1] + bV.y,
                            acc[1][2] + bV.z, acc[1][3] + bV.w);
            *(float4*)(sw + QS_OFF + t * 16 + c4) =
                make_float4((acc[2][0] + bQ.x) * 0.25f, (acc[2][1] + bQ.y) * 0.25f,
                            (acc[2][2] + bQ.z) * 0.25f, (acc[2][3] + bQ.w) * 0.25f);
        }
        __syncthreads();
    }

    // ---- phase 2: scores + softmax (no max-subtract; bounded scores), column sums ----
    float wacc[7];
#pragma unroll
    for (int m = 0; m < 7; m++) wacc[m] = 0.f;

    for (int qb = wid * 4; qb < len; qb += 32) {
        float qv[4][16];
#pragma unroll
        for (int qq = 0; qq < 4; qq++) {
            int q = qb + qq; q = (q < len) ? q : 0;
            const float4* p = (const float4*)(sw + QS_OFF + q * 16);
#pragma unroll
            for (int jj = 0; jj < 4; jj++) {
                float4 v = p[jj];
                qv[qq][4 * jj + 0] = v.x; qv[qq][4 * jj + 1] = v.y;
                qv[qq][4 * jj + 2] = v.z; qv[qq][4 * jj + 3] = v.w;
            }
        }

        float ee[7][4];
#pragma unroll
        for (int m = 0; m < 7; m++) {
            int k = m * 32 + lane;
            if (m * 32 < len) {                  // warp-uniform block guard
                if (k < len) {
                    const float* kp = sw + KT_OFF + k;
                    float a0 = 0.f, a1 = 0.f, a2 = 0.f, a3 = 0.f;
#pragma unroll
                    for (int j = 0; j < 16; j++) {
                        float kw = kp[j * KTS];
                        a0 = fmaf(kw, qv[0][j], a0);
                        a1 = fmaf(kw, qv[1][j], a1);
                        a2 = fmaf(kw, qv[2][j], a2);
                        a3 = fmaf(kw, qv[3][j], a3);
                    }
                    ee[m][0] = __expf(a0); ee[m][1] = __expf(a1);
                    ee[m][2] = __expf(a2); ee[m][3] = __expf(a3);
                } else {
                    ee[m][0] = 0.f; ee[m][1] = 0.f; ee[m][2] = 0.f; ee[m][3] = 0.f;
                }
            } else {
                ee[m][0] = 0.f; ee[m][1] = 0.f; ee[m][2] = 0.f; ee[m][3] = 0.f;
            }
        }

        // per-q row sums (tree), then 4 interleaved warp reductions
        float z[4];
#pragma unroll
        for (int qq = 0; qq < 4; qq++) {
            float s01 = ee[0][qq] + ee[1][qq];
            float s23 = ee[2][qq] + ee[3][qq];
            float s45 = ee[4][qq] + ee[5][qq];
            z[qq] = (s01 + s23) + (s45 + ee[6][qq]);
        }
#pragma unroll
        for (int o = 16; o; o >>= 1) {
            z[0] += __shfl_xor_sync(0xffffffffu, z[0], o);
            z[1] += __shfl_xor_sync(0xffffffffu, z[1], o);
            z[2] += __shfl_xor_sync(0xffffffffu, z[2], o);
            z[3] += __shfl_xor_sync(0xffffffffu, z[3], o);
        }
        float inv[4];
#pragma unroll
        for (int qq = 0; qq < 4; qq++)
            inv[qq] = (qb + qq < len) ? __fdividef(1.0f, z[qq]) : 0.0f;
#pragma unroll
        for (int m = 0; m < 7; m++) {
            float t0 = fmaf(ee[m][0], inv[0], wacc[m]);
            float t1 = fmaf(ee[m][1], inv[1], t0);
            float t2 = fmaf(ee[m][2], inv[2], t1);
            wacc[m]  = fmaf(ee[m][3], inv[3], t2);
        }
    }

#pragma unroll
    for (int m = 0; m < 7; m++) {
        int k = m * 32 + lane;
        if (k < Lc) atomicAdd(&sw[WC_OFF + k], wacc[m]);
    }
    __syncthreads();

    // ---- phase 3: S[c] = sum_k wc[k] * V[k][c] ----
    {
        const int c = tid & 15, part = tid >> 4;
        float acc = 0.f;
        for (int k = part; k < len; k += 16)
            acc = fmaf(sw[WC_OFF + k], sw[VS_OFF + k * 16 + c], acc);
        sw[SP_OFF + part * 16 + c] = acc;
    }
    __syncthreads();
    if (tid < 16) {
        float s = 0.f;
#pragma unroll
        for (int p = 0; p < 16; p++) s += sw[SP_OFF + p * 16 + tid];
        g_S[b * 64 + h * 16 + tid] = s;
    }
    if (tid == 0 && h == 0) g_len[b] = len;
}

// ---------------- kernel 2: out = (S @ WfT + bf*len) / (len+1e-8) ----------------
__global__ void __launch_bounds__(256)
pool_proj_kernel(const float* __restrict__ Wf, const float* __restrict__ bf,
                 float* __restrict__ out) {
    __shared__ float wf[64 * 65];
    __shared__ float ss[4 * 64];
    const int tid = threadIdx.x;
    const int b0 = blockIdx.x * 4;

    for (int idx = tid; idx < 4096; idx += 256) {
        int e = idx >> 6, c = idx & 63;
        wf[e * 65 + c] = Wf[idx];
    }
    ss[tid] = g_S[b0 * 64 + tid];
    __syncthreads();

    const int bb = tid >> 6, e = tid & 63;
    float acc = 0.f;
#pragma unroll 16
    for (int c = 0; c < 64; c++)
        acc = fmaf(ss[bb * 64 + c], wf[e * 65 + c], acc);
    const float lenf = (float)g_len[b0 + bb];
    const float invd = 1.0f / (lenf + 1e-8f);
    out[(b0 + bb) * 64 + e] = acc * invd + bf[e] * lenf * invd;
}

extern "C" void kernel_launch(void* const* d_in, const int* in_sizes, int n_in,
                              void* d_out, int out_size) {
    const float* input   = (const float*)d_in[0];
    const int*   mask    = (const int*)d_in[1];
    const float* pos_enc = (const float*)d_in[2];
    const float* Wk      = (const float*)d_in[3];
    const float* bk      = (const float*)d_in[4];
    const float* Wv      = (const float*)d_in[5];
    const float* bv      = (const float*)d_in[6];
    const float* Wq      = (const float*)d_in[7];
    const float* bq      = (const float*)d_in[8];
    const float* Wf      = (const float*)d_in[9];
    const float* bf      = (const float*)d_in[10];
    float* out           = (float*)d_out;

    const size_t smem1 = (size_t)SM1_F * sizeof(float);
    cudaFuncSetAttribute(attn_head_kernel,
                         cudaFuncAttributeMaxDynamicSharedMemorySize, (int)smem1);
    attn_head_kernel<<<Bc * 4, 256, smem1>>>(input, mask, pos_enc,
                                             Wk, bk, Wv, bv, Wq, bq);
    pool_proj_kernel<<<Bc / 4, 256>>>(Wf, bf, out);
}